// round 8
// baseline (speedup 1.0000x reference)
#include <cuda_runtime.h>

typedef unsigned long long ull;

// ---------------- problem constants ------------------------------------------
#define MAX_N 100000
#define MAX_E 1600000
#define MAXDEG 128           // Poisson(16): P(deg>127) ~ 0; guarded anyway
#define LOG2_MAXDEG 7

// ---------------- device scratch (allocation-free; static zero-init) ----------
__device__ int   g_cur[MAX_N];                 // bucket cursor == degree after pass
__device__ float g_dis[MAX_N];                 // (deg+1)^{-1/2}
__device__ int   g_eslot[MAX_N * MAXDEG];      // fixed-stride CSR: src ids
__device__ __align__(16) float g_bufA[MAX_N * 96];
__device__ __align__(16) float g_bufB[MAX_N * 96];
__device__ __align__(16) float g_bufH[MAX_N * 96];

// ---------------- packed f32x2 helpers ----------------------------------------
__device__ __forceinline__ ull pack2(float x) {
    ull r;
    asm("mov.b64 %0, {%1, %1};" : "=l"(r) : "r"(__float_as_uint(x)));
    return r;
}
__device__ __forceinline__ ull fma2(ull a, ull b, ull c) {
    ull d;
    asm("fma.rn.f32x2 %0, %1, %2, %3;" : "=l"(d) : "l"(a), "l"(b), "l"(c));
    return d;
}

// ---------------- single-pass bucket+count ------------------------------------
// edge_index is INT32 (JAX x64 disabled). g_cur must be zero on entry
// (static init on call 1; k_zero_tail re-zeroes at the end of every call).
__global__ void k_bucketcount(const int* __restrict__ ei, int e, int n) {
    int i = blockIdx.x * blockDim.x + threadIdx.x;
    if (i >= e) return;
    int s = ei[i];
    int d = ei[e + i];
    if ((unsigned)s >= (unsigned)n) s = 0;   // surface as rel_err, never trap
    if ((unsigned)d >= (unsigned)n) d = 0;
    int pos = atomicAdd(&g_cur[d], 1);
    if (pos < MAXDEG) g_eslot[(d << LOG2_MAXDEG) + pos] = s;
}

__global__ void k_dis(int n) {
    int i = blockIdx.x * blockDim.x + threadIdx.x;
    if (i < n) g_dis[i] = rsqrtf((float)g_cur[i] + 1.0f);
}

__global__ void k_zero_tail(int n) {
    int i = blockIdx.x * blockDim.x + threadIdx.x;
    if (i < n) g_cur[i] = 0;
}

// ---------------- gather aggregation: out[v] = sum + h[v]*dis^2 (+bias) -------
// G = F/4 threads per node; norm computed inline (dis[src] * dis[node]).
template <int F, bool BIAS>
__global__ void __launch_bounds__(256)
k_agg(const float* __restrict__ h, const float* __restrict__ bias,
      float* __restrict__ out, int n) {
    constexpr int G = F / 4;
    int tid = blockIdx.x * blockDim.x + threadIdx.x;
    int node = tid / G;
    int v = tid - node * G;
    if (node >= n) return;

    float dn = g_dis[node];
    float d2 = dn * dn;
    float4 acc = *reinterpret_cast<const float4*>(h + (size_t)node * F + (v << 2));
    acc.x *= d2; acc.y *= d2; acc.z *= d2; acc.w *= d2;
    if (BIAS) {
        float4 bv = *reinterpret_cast<const float4*>(bias + (v << 2));
        acc.x += bv.x; acc.y += bv.y; acc.z += bv.z; acc.w += bv.w;
    }

    int deg = g_cur[node];
    if (deg > MAXDEG) deg = MAXDEG;
    const int* slots = g_eslot + ((size_t)node << LOG2_MAXDEG);

    int j = 0;
    for (; j + 4 <= deg; j += 4) {
        int4 s4 = *reinterpret_cast<const int4*>(slots + j);   // 16B-aligned
        float w0 = g_dis[s4.x] * dn;
        float w1 = g_dis[s4.y] * dn;
        float w2 = g_dis[s4.z] * dn;
        float w3 = g_dis[s4.w] * dn;
        float4 a0 = *reinterpret_cast<const float4*>(h + (size_t)s4.x * F + (v << 2));
        float4 a1 = *reinterpret_cast<const float4*>(h + (size_t)s4.y * F + (v << 2));
        float4 a2 = *reinterpret_cast<const float4*>(h + (size_t)s4.z * F + (v << 2));
        float4 a3 = *reinterpret_cast<const float4*>(h + (size_t)s4.w * F + (v << 2));
        acc.x += a0.x * w0; acc.y += a0.y * w0; acc.z += a0.z * w0; acc.w += a0.w * w0;
        acc.x += a1.x * w1; acc.y += a1.y * w1; acc.z += a1.z * w1; acc.w += a1.w * w1;
        acc.x += a2.x * w2; acc.y += a2.y * w2; acc.z += a2.z * w2; acc.w += a2.w * w2;
        acc.x += a3.x * w3; acc.y += a3.y * w3; acc.z += a3.z * w3; acc.w += a3.w * w3;
    }
    for (; j < deg; j++) {
        int s = slots[j];
        float w = g_dis[s] * dn;
        float4 a = *reinterpret_cast<const float4*>(h + (size_t)s * F + (v << 2));
        acc.x += a.x * w; acc.y += a.y * w; acc.z += a.z * w; acc.w += a.w * w;
    }
    *reinterpret_cast<float4*>(out + (size_t)node * F + (v << 2)) = acc;
}

// ---------------- GEMM: out = act(in) @ W (+bh), packed f32x2 FMA --------------
template <int FIN, int FOUT, bool RELU, bool BIASH>
__global__ void __launch_bounds__(128)
k_gemm(const float* __restrict__ in, const float* __restrict__ W,
       const float* __restrict__ bh, float* __restrict__ out, int n) {
    extern __shared__ float sm[];
    float* Xs = sm;                 // [FIN][129]
    float* Ws = sm + FIN * 129;     // [FIN][FOUT]
    const int tid = threadIdx.x;
    const int base = blockIdx.x * 128;

    for (int i = tid; i < FIN * FOUT; i += 128) Ws[i] = W[i];

    const int rows = (n - base < 128) ? (n - base) : 128;
    for (int i = tid; i < FIN * 128; i += 128) {
        int nl = i / FIN;
        int k = i - nl * FIN;
        float v = 0.0f;
        if (nl < rows) {
            v = in[(size_t)(base + nl) * FIN + k];
            if (RELU) v = fmaxf(v, 0.0f);
        }
        Xs[k * 129 + nl] = v;
    }
    __syncthreads();

    const int node = base + tid;
    const bool valid = node < n;

    constexpr int CH = (FOUT % 32 == 0) ? 32 : FOUT;   // 32 or 16
    constexpr int NP = CH / 2;

    for (int c0 = 0; c0 < FOUT; c0 += CH) {
        ull acc[NP];
#pragma unroll
        for (int j = 0; j < NP; j++)
            acc[j] = BIASH ? *reinterpret_cast<const ull*>(bh + c0 + 2 * j) : 0ull;

#pragma unroll 4
        for (int k = 0; k < FIN; k++) {
            ull xx = pack2(Xs[k * 129 + tid]);
            const ull* wr = reinterpret_cast<const ull*>(Ws + k * FOUT + c0);
#pragma unroll
            for (int j = 0; j < NP; j++)
                acc[j] = fma2(xx, wr[j], acc[j]);
        }

        if (valid) {
            ull* op = reinterpret_cast<ull*>(out + (size_t)node * FOUT + c0);
#pragma unroll
            for (int j = 0; j < NP; j++) op[j] = acc[j];
        }
    }
}

// ---------------- launch -------------------------------------------------------
extern "C" void kernel_launch(void* const* d_in, const int* in_sizes, int n_in,
                              void* d_out, int out_size) {
    const float* x  = (const float*)d_in[0];
    const int*   ei = (const int*)d_in[1];   // int32
    const float* W1 = (const float*)d_in[2]; const float* b1 = (const float*)d_in[3];
    const float* W2 = (const float*)d_in[4]; const float* b2 = (const float*)d_in[5];
    const float* W3 = (const float*)d_in[6]; const float* b3 = (const float*)d_in[7];
    const float* W4 = (const float*)d_in[8]; const float* b4 = (const float*)d_in[9];
    float* out = (float*)d_out;

    const int n = in_sizes[0] / 64;
    const int e = in_sizes[1] / 2;

    float *bufA, *bufB, *bufH;
    cudaGetSymbolAddress((void**)&bufA, g_bufA);
    cudaGetSymbolAddress((void**)&bufB, g_bufB);
    cudaGetSymbolAddress((void**)&bufH, g_bufH);

    const int s1 = (64 * 129 + 64 * 96) * 4;
    const int s2 = (96 * 129 + 96 * 64) * 4;
    const int s3 = (64 * 129 + 64 * 32) * 4;
    const int s4 = (32 * 129 + 32 * 16) * 4;
    cudaFuncSetAttribute(k_gemm<64, 96, false, true>, cudaFuncAttributeMaxDynamicSharedMemorySize, s1);
    cudaFuncSetAttribute(k_gemm<96, 64, true, false>, cudaFuncAttributeMaxDynamicSharedMemorySize, s2);
    cudaFuncSetAttribute(k_gemm<64, 32, true, false>, cudaFuncAttributeMaxDynamicSharedMemorySize, s3);
    cudaFuncSetAttribute(k_gemm<32, 16, true, false>, cudaFuncAttributeMaxDynamicSharedMemorySize, s4);

    const int TB = 256;
    const int nb_n = (n + TB - 1) / TB;
    const int nb_e = (e + TB - 1) / TB;
    const int gblk = (n + 127) / 128;

    // ---- CSR build: single edge pass (g_cur is zero on entry) ----
    k_bucketcount<<<nb_e, TB>>>(ei, e, n);
    k_dis<<<nb_n, TB>>>(n);

    // ---- layer 1: agg1 = Ax (width 64), then GEMM 64->96 (+b1) ----
    k_agg<64, false><<<(n * 16 + TB - 1) / TB, TB>>>(x, nullptr, bufA, n);
    k_gemm<64, 96, false, true><<<gblk, 128, s1>>>(bufA, W1, b1, bufB, n);

    // ---- layer 2: t = relu(h1)@W2 ; agg2 = A t + b2 ----
    k_gemm<96, 64, true, false><<<gblk, 128, s2>>>(bufB, W2, nullptr, bufH, n);
    k_agg<64, true><<<(n * 16 + TB - 1) / TB, TB>>>(bufH, b2, bufA, n);

    // ---- layer 3: t = relu(agg2)@W3 ; agg3 = A t + b3 ----
    k_gemm<64, 32, true, false><<<gblk, 128, s3>>>(bufA, W3, nullptr, bufH, n);
    k_agg<32, true><<<(n * 8 + TB - 1) / TB, TB>>>(bufH, b3, bufB, n);

    // ---- layer 4: t = relu(agg3)@W4 ; out = A t + b4 ----
    k_gemm<32, 16, true, false><<<gblk, 128, s4>>>(bufB, W4, nullptr, bufH, n);
    k_agg<16, true><<<(n * 4 + TB - 1) / TB, TB>>>(bufH, b4, out, n);

    // ---- reset cursor for the next (deterministic) replay ----
    k_zero_tail<<<nb_n, TB>>>(n);
}

// round 9
// speedup vs baseline: 1.0789x; 1.0789x over previous
#include <cuda_runtime.h>

typedef unsigned long long ull;

// ---------------- problem constants ------------------------------------------
#define MAX_N 100000
#define MAX_E 1600000
#define MAXDEG 128           // Poisson(16): P(deg>127) ~ 0; guarded anyway
#define LOG2_MAXDEG 7

// ---------------- device scratch (allocation-free; static zero-init) ----------
__device__ int   g_cur[MAX_N];                 // bucket cursor == degree after pass
__device__ float g_dis[MAX_N];                 // (deg+1)^{-1/2}
__device__ int   g_eslot[MAX_N * MAXDEG];      // fixed-stride CSR: src ids
__device__ __align__(16) float g_bufA[MAX_N * 96];
__device__ __align__(16) float g_bufB[MAX_N * 96];
__device__ __align__(16) float g_bufH[MAX_N * 96];

// ---------------- packed f32x2 helpers ----------------------------------------
__device__ __forceinline__ ull pack2(float x) {
    ull r;
    asm("mov.b64 %0, {%1, %1};" : "=l"(r) : "r"(__float_as_uint(x)));
    return r;
}
__device__ __forceinline__ ull fma2(ull a, ull b, ull c) {
    ull d;
    asm("fma.rn.f32x2 %0, %1, %2, %3;" : "=l"(d) : "l"(a), "l"(b), "l"(c));
    return d;
}

// ---------------- single-pass bucket+count ------------------------------------
// edge_index is INT32 (JAX x64 disabled). g_cur must be zero on entry
// (static init on call 1; k_zero_tail re-zeroes at the end of every call).
__global__ void k_bucketcount(const int* __restrict__ ei, int e, int n) {
    int i = blockIdx.x * blockDim.x + threadIdx.x;
    if (i >= e) return;
    int s = ei[i];
    int d = ei[e + i];
    if ((unsigned)s >= (unsigned)n) s = 0;   // surface as rel_err, never trap
    if ((unsigned)d >= (unsigned)n) d = 0;
    int pos = atomicAdd(&g_cur[d], 1);
    if (pos < MAXDEG) g_eslot[(d << LOG2_MAXDEG) + pos] = s;
}

__global__ void k_dis(int n) {
    int i = blockIdx.x * blockDim.x + threadIdx.x;
    if (i < n) g_dis[i] = rsqrtf((float)g_cur[i] + 1.0f);
}

__global__ void k_zero_tail(int n) {
    int i = blockIdx.x * blockDim.x + threadIdx.x;
    if (i < n) g_cur[i] = 0;
}

// ---------------- gather aggregation: out[v] = sum + h[v]*dis^2 (+bias) -------
template <int F, bool BIAS>
__global__ void __launch_bounds__(256)
k_agg(const float* __restrict__ h, const float* __restrict__ bias,
      float* __restrict__ out, int n) {
    constexpr int G = F / 4;
    int tid = blockIdx.x * blockDim.x + threadIdx.x;
    int node = tid / G;
    int v = tid - node * G;
    if (node >= n) return;

    float dn = g_dis[node];
    float d2 = dn * dn;
    float4 acc = *reinterpret_cast<const float4*>(h + (size_t)node * F + (v << 2));
    acc.x *= d2; acc.y *= d2; acc.z *= d2; acc.w *= d2;
    if (BIAS) {
        float4 bv = *reinterpret_cast<const float4*>(bias + (v << 2));
        acc.x += bv.x; acc.y += bv.y; acc.z += bv.z; acc.w += bv.w;
    }

    int deg = g_cur[node];
    if (deg > MAXDEG) deg = MAXDEG;
    const int* slots = g_eslot + ((size_t)node << LOG2_MAXDEG);

    int j = 0;
    for (; j + 4 <= deg; j += 4) {
        int4 s4 = *reinterpret_cast<const int4*>(slots + j);   // 16B-aligned
        float w0 = g_dis[s4.x] * dn;
        float w1 = g_dis[s4.y] * dn;
        float w2 = g_dis[s4.z] * dn;
        float w3 = g_dis[s4.w] * dn;
        float4 a0 = *reinterpret_cast<const float4*>(h + (size_t)s4.x * F + (v << 2));
        float4 a1 = *reinterpret_cast<const float4*>(h + (size_t)s4.y * F + (v << 2));
        float4 a2 = *reinterpret_cast<const float4*>(h + (size_t)s4.z * F + (v << 2));
        float4 a3 = *reinterpret_cast<const float4*>(h + (size_t)s4.w * F + (v << 2));
        acc.x += a0.x * w0; acc.y += a0.y * w0; acc.z += a0.z * w0; acc.w += a0.w * w0;
        acc.x += a1.x * w1; acc.y += a1.y * w1; acc.z += a1.z * w1; acc.w += a1.w * w1;
        acc.x += a2.x * w2; acc.y += a2.y * w2; acc.z += a2.z * w2; acc.w += a2.w * w2;
        acc.x += a3.x * w3; acc.y += a3.y * w3; acc.z += a3.z * w3; acc.w += a3.w * w3;
    }
    for (; j < deg; j++) {
        int s = slots[j];
        float w = g_dis[s] * dn;
        float4 a = *reinterpret_cast<const float4*>(h + (size_t)s * F + (v << 2));
        acc.x += a.x * w; acc.y += a.y * w; acc.z += a.z * w; acc.w += a.w * w;
    }
    *reinterpret_cast<float4*>(out + (size_t)node * F + (v << 2)) = acc;
}

// ---------------- GEMM: out = act(in) @ W (+bh), packed f32x2 FMA --------------
// 256 threads, 128-node tile. Thread halves split FOUT columns (same smem,
// 2x warps -> 2x occupancy vs 128-thread version). Single acc chunk per half.
template <int FIN, int FOUT, bool RELU, bool BIASH>
__global__ void __launch_bounds__(256)
k_gemm(const float* __restrict__ in, const float* __restrict__ W,
       const float* __restrict__ bh, float* __restrict__ out, int n) {
    extern __shared__ float sm[];
    float* Xs = sm;                 // [FIN][129]
    float* Ws = sm + FIN * 129;     // [FIN][FOUT]
    const int tid = threadIdx.x;
    const int base = blockIdx.x * 128;

    for (int i = tid; i < FIN * FOUT; i += 256) Ws[i] = W[i];

    const int rows = (n - base < 128) ? (n - base) : 128;
    for (int i = tid; i < FIN * 128; i += 256) {
        int nl = i / FIN;
        int k = i - nl * FIN;
        float v = 0.0f;
        if (nl < rows) {
            v = in[(size_t)(base + nl) * FIN + k];
            if (RELU) v = fmaxf(v, 0.0f);
        }
        Xs[k * 129 + nl] = v;
    }
    __syncthreads();

    const int lane = tid & 127;            // node within tile
    const int half = tid >> 7;             // column half
    const int node = base + lane;
    const bool valid = node < n;

    constexpr int CH = FOUT / 2;           // 48 / 32 / 16 / 8 columns per half
    constexpr int NP = CH / 2;             // packed accumulators (24/16/8/4)
    const int c0 = half * CH;

    ull acc[NP];
#pragma unroll
    for (int j = 0; j < NP; j++)
        acc[j] = BIASH ? *reinterpret_cast<const ull*>(bh + c0 + 2 * j) : 0ull;

#pragma unroll 4
    for (int k = 0; k < FIN; k++) {
        ull xx = pack2(Xs[k * 129 + lane]);
        const ull* wr = reinterpret_cast<const ull*>(Ws + k * FOUT + c0);
#pragma unroll
        for (int j = 0; j < NP; j++)
            acc[j] = fma2(xx, wr[j], acc[j]);
    }

    if (valid) {
        ull* op = reinterpret_cast<ull*>(out + (size_t)node * FOUT + c0);
#pragma unroll
        for (int j = 0; j < NP; j++) op[j] = acc[j];
    }
}

// ---------------- launch -------------------------------------------------------
extern "C" void kernel_launch(void* const* d_in, const int* in_sizes, int n_in,
                              void* d_out, int out_size) {
    const float* x  = (const float*)d_in[0];
    const int*   ei = (const int*)d_in[1];   // int32
    const float* W1 = (const float*)d_in[2]; const float* b1 = (const float*)d_in[3];
    const float* W2 = (const float*)d_in[4]; const float* b2 = (const float*)d_in[5];
    const float* W3 = (const float*)d_in[6]; const float* b3 = (const float*)d_in[7];
    const float* W4 = (const float*)d_in[8]; const float* b4 = (const float*)d_in[9];
    float* out = (float*)d_out;

    const int n = in_sizes[0] / 64;
    const int e = in_sizes[1] / 2;

    float *bufA, *bufB, *bufH;
    cudaGetSymbolAddress((void**)&bufA, g_bufA);
    cudaGetSymbolAddress((void**)&bufB, g_bufB);
    cudaGetSymbolAddress((void**)&bufH, g_bufH);

    const int s1 = (64 * 129 + 64 * 96) * 4;
    const int s2 = (96 * 129 + 96 * 64) * 4;
    const int s3 = (64 * 129 + 64 * 32) * 4;
    const int s4 = (32 * 129 + 32 * 16) * 4;
    cudaFuncSetAttribute(k_gemm<64, 96, false, true>, cudaFuncAttributeMaxDynamicSharedMemorySize, s1);
    cudaFuncSetAttribute(k_gemm<96, 64, true, false>, cudaFuncAttributeMaxDynamicSharedMemorySize, s2);
    cudaFuncSetAttribute(k_gemm<64, 32, true, false>, cudaFuncAttributeMaxDynamicSharedMemorySize, s3);
    cudaFuncSetAttribute(k_gemm<32, 16, true, false>, cudaFuncAttributeMaxDynamicSharedMemorySize, s4);

    const int TB = 256;
    const int nb_n = (n + TB - 1) / TB;
    const int nb_e = (e + TB - 1) / TB;
    const int gblk = (n + 127) / 128;

    // ---- CSR build: single edge pass (g_cur is zero on entry) ----
    k_bucketcount<<<nb_e, TB>>>(ei, e, n);
    k_dis<<<nb_n, TB>>>(n);

    // ---- layer 1: agg1 = Ax (width 64), then GEMM 64->96 (+b1) ----
    k_agg<64, false><<<(n * 16 + TB - 1) / TB, TB>>>(x, nullptr, bufA, n);
    k_gemm<64, 96, false, true><<<gblk, 256, s1>>>(bufA, W1, b1, bufB, n);

    // ---- layer 2: t = relu(h1)@W2 ; agg2 = A t + b2 ----
    k_gemm<96, 64, true, false><<<gblk, 256, s2>>>(bufB, W2, nullptr, bufH, n);
    k_agg<64, true><<<(n * 16 + TB - 1) / TB, TB>>>(bufH, b2, bufA, n);

    // ---- layer 3: t = relu(agg2)@W3 ; agg3 = A t + b3 ----
    k_gemm<64, 32, true, false><<<gblk, 256, s3>>>(bufA, W3, nullptr, bufH, n);
    k_agg<32, true><<<(n * 8 + TB - 1) / TB, TB>>>(bufH, b3, bufB, n);

    // ---- layer 4: t = relu(agg3)@W4 ; out = A t + b4 ----
    k_gemm<32, 16, true, false><<<gblk, 256, s4>>>(bufB, W4, nullptr, bufH, n);
    k_agg<16, true><<<(n * 4 + TB - 1) / TB, TB>>>(bufH, b4, out, n);

    // ---- reset cursor for the next (deterministic) replay ----
    k_zero_tail<<<nb_n, TB>>>(n);
}

// round 10
// speedup vs baseline: 1.1480x; 1.0641x over previous
#include <cuda_runtime.h>

typedef unsigned long long ull;

// ---------------- problem constants ------------------------------------------
#define MAX_N 100000
#define MAX_E 1600000
#define MAXDEG 128           // Poisson(16): P(deg>127) ~ 0; guarded anyway
#define LOG2_MAXDEG 7

// ---------------- device scratch (allocation-free; static zero-init) ----------
__device__ int   g_cur[MAX_N];                 // bucket cursor == degree after pass
__device__ float g_dis[MAX_N];                 // (deg+1)^{-1/2}
__device__ int   g_eslot[MAX_N * MAXDEG];      // fixed-stride CSR: src ids
__device__ __align__(16) float g_bufA[MAX_N * 96];
__device__ __align__(16) float g_bufB[MAX_N * 96];
__device__ __align__(16) float g_bufH[MAX_N * 96];

// ---------------- packed f32x2 helpers ----------------------------------------
__device__ __forceinline__ ull pack2(float x) {
    ull r;
    asm("mov.b64 %0, {%1, %1};" : "=l"(r) : "r"(__float_as_uint(x)));
    return r;
}
__device__ __forceinline__ ull fma2(ull a, ull b, ull c) {
    ull d;
    asm("fma.rn.f32x2 %0, %1, %2, %3;" : "=l"(d) : "l"(a), "l"(b), "l"(c));
    return d;
}

// ---------------- single-pass bucket+count ------------------------------------
// edge_index is INT32 (JAX x64 disabled). g_cur must be zero on entry
// (static init on call 1; k_zero_tail re-zeroes at the end of every call).
__global__ void k_bucketcount(const int* __restrict__ ei, int e, int n) {
    int i = blockIdx.x * blockDim.x + threadIdx.x;
    if (i >= e) return;
    int s = ei[i];
    int d = ei[e + i];
    if ((unsigned)s >= (unsigned)n) s = 0;   // surface as rel_err, never trap
    if ((unsigned)d >= (unsigned)n) d = 0;
    int pos = atomicAdd(&g_cur[d], 1);
    if (pos < MAXDEG) g_eslot[(d << LOG2_MAXDEG) + pos] = s;
}

__global__ void k_dis(int n) {
    int i = blockIdx.x * blockDim.x + threadIdx.x;
    if (i < n) g_dis[i] = rsqrtf((float)g_cur[i] + 1.0f);
}

__global__ void k_zero_tail(int n) {
    int i = blockIdx.x * blockDim.x + threadIdx.x;
    if (i < n) g_cur[i] = 0;
}

// ---------------- gather aggregation: out[v] = sum + h[v]*dis^2 (+bias) -------
template <int F, bool BIAS>
__global__ void __launch_bounds__(256)
k_agg(const float* __restrict__ h, const float* __restrict__ bias,
      float* __restrict__ out, int n) {
    constexpr int G = F / 4;
    int tid = blockIdx.x * blockDim.x + threadIdx.x;
    int node = tid / G;
    int v = tid - node * G;
    if (node >= n) return;

    float dn = g_dis[node];
    float d2 = dn * dn;
    float4 acc = *reinterpret_cast<const float4*>(h + (size_t)node * F + (v << 2));
    acc.x *= d2; acc.y *= d2; acc.z *= d2; acc.w *= d2;
    if (BIAS) {
        float4 bv = *reinterpret_cast<const float4*>(bias + (v << 2));
        acc.x += bv.x; acc.y += bv.y; acc.z += bv.z; acc.w += bv.w;
    }

    int deg = g_cur[node];
    if (deg > MAXDEG) deg = MAXDEG;
    const int* slots = g_eslot + ((size_t)node << LOG2_MAXDEG);

    int j = 0;
    for (; j + 4 <= deg; j += 4) {
        int4 s4 = *reinterpret_cast<const int4*>(slots + j);   // 16B-aligned
        float w0 = g_dis[s4.x] * dn;
        float w1 = g_dis[s4.y] * dn;
        float w2 = g_dis[s4.z] * dn;
        float w3 = g_dis[s4.w] * dn;
        float4 a0 = *reinterpret_cast<const float4*>(h + (size_t)s4.x * F + (v << 2));
        float4 a1 = *reinterpret_cast<const float4*>(h + (size_t)s4.y * F + (v << 2));
        float4 a2 = *reinterpret_cast<const float4*>(h + (size_t)s4.z * F + (v << 2));
        float4 a3 = *reinterpret_cast<const float4*>(h + (size_t)s4.w * F + (v << 2));
        acc.x += a0.x * w0; acc.y += a0.y * w0; acc.z += a0.z * w0; acc.w += a0.w * w0;
        acc.x += a1.x * w1; acc.y += a1.y * w1; acc.z += a1.z * w1; acc.w += a1.w * w1;
        acc.x += a2.x * w2; acc.y += a2.y * w2; acc.z += a2.z * w2; acc.w += a2.w * w2;
        acc.x += a3.x * w3; acc.y += a3.y * w3; acc.z += a3.z * w3; acc.w += a3.w * w3;
    }
    for (; j < deg; j++) {
        int s = slots[j];
        float w = g_dis[s] * dn;
        float4 a = *reinterpret_cast<const float4*>(h + (size_t)s * F + (v << 2));
        acc.x += a.x * w; acc.y += a.y * w; acc.z += a.z * w; acc.w += a.w * w;
    }
    *reinterpret_cast<float4*>(out + (size_t)node * F + (v << 2)) = acc;
}

// ---------------- GEMM: out = act(in) @ W (+bh), packed f32x2 FMA --------------
// 64-node tile, 256 threads = 4 col-groups x 64 nodes. Xs node-major [64][FIN+1]
// (stride-65 scalar reads = conflict-free); Ws broadcast. Small smem + ~50 regs
// -> 4-5 blocks/SM for latency hiding.
template <int FIN, int FOUT, bool RELU, bool BIASH>
__global__ void __launch_bounds__(256)
k_gemm(const float* __restrict__ in, const float* __restrict__ W,
       const float* __restrict__ bh, float* __restrict__ out, int n) {
    constexpr int XP = FIN + 1;          // padded row
    extern __shared__ float sm[];
    float* Xs = sm;                      // [64][XP]
    float* Ws = sm + 64 * XP;            // [FIN][FOUT]
    const int tid = threadIdx.x;
    const int base = blockIdx.x * 64;

    for (int i = tid; i < FIN * FOUT; i += 256) Ws[i] = W[i];

    const int rows = (n - base < 64) ? (n - base) : 64;
    constexpr int KQ = FIN / 4;
    for (int i = tid; i < 64 * KQ; i += 256) {
        int nl = i / KQ;
        int kq = i - nl * KQ;
        float4 v = {0.f, 0.f, 0.f, 0.f};
        if (nl < rows) {
            v = *reinterpret_cast<const float4*>(in + (size_t)(base + nl) * FIN + 4 * kq);
            if (RELU) {
                v.x = fmaxf(v.x, 0.f); v.y = fmaxf(v.y, 0.f);
                v.z = fmaxf(v.z, 0.f); v.w = fmaxf(v.w, 0.f);
            }
        }
        float* xr = Xs + nl * XP + 4 * kq;
        xr[0] = v.x; xr[1] = v.y; xr[2] = v.z; xr[3] = v.w;
    }
    __syncthreads();

    const int lane = tid & 63;           // node within tile
    const int cg = tid >> 6;             // column group (0..3)
    const int node = base + lane;
    const bool valid = node < n;

    constexpr int CH = FOUT / 4;         // 24 / 16 / 8 / 4 cols per thread
    constexpr int NP = CH / 2;           // packed accumulators (12/8/4/2)
    const int c0 = cg * CH;

    ull acc[NP];
#pragma unroll
    for (int j = 0; j < NP; j++)
        acc[j] = BIASH ? *reinterpret_cast<const ull*>(bh + c0 + 2 * j) : 0ull;

    const float* xrow = Xs + lane * XP;
#pragma unroll 4
    for (int k = 0; k < FIN; k++) {
        ull xx = pack2(xrow[k]);
        const ull* wr = reinterpret_cast<const ull*>(Ws + k * FOUT + c0);
#pragma unroll
        for (int j = 0; j < NP; j++)
            acc[j] = fma2(xx, wr[j], acc[j]);
    }

    if (valid) {
        ull* op = reinterpret_cast<ull*>(out + (size_t)node * FOUT + c0);
#pragma unroll
        for (int j = 0; j < NP; j++) op[j] = acc[j];
    }
}

// ---------------- launch -------------------------------------------------------
extern "C" void kernel_launch(void* const* d_in, const int* in_sizes, int n_in,
                              void* d_out, int out_size) {
    const float* x  = (const float*)d_in[0];
    const int*   ei = (const int*)d_in[1];   // int32
    const float* W1 = (const float*)d_in[2]; const float* b1 = (const float*)d_in[3];
    const float* W2 = (const float*)d_in[4]; const float* b2 = (const float*)d_in[5];
    const float* W3 = (const float*)d_in[6]; const float* b3 = (const float*)d_in[7];
    const float* W4 = (const float*)d_in[8]; const float* b4 = (const float*)d_in[9];
    float* out = (float*)d_out;

    const int n = in_sizes[0] / 64;
    const int e = in_sizes[1] / 2;

    float *bufA, *bufB, *bufH;
    cudaGetSymbolAddress((void**)&bufA, g_bufA);
    cudaGetSymbolAddress((void**)&bufB, g_bufB);
    cudaGetSymbolAddress((void**)&bufH, g_bufH);

    const int s1 = (64 * 65 + 64 * 96) * 4;   // 41216
    const int s2 = (64 * 97 + 96 * 64) * 4;   // 49408
    const int s3 = (64 * 65 + 64 * 32) * 4;   // 24832
    const int s4 = (64 * 33 + 32 * 16) * 4;   // 10496
    cudaFuncSetAttribute(k_gemm<64, 96, false, true>, cudaFuncAttributeMaxDynamicSharedMemorySize, s1);
    cudaFuncSetAttribute(k_gemm<96, 64, true, false>, cudaFuncAttributeMaxDynamicSharedMemorySize, s2);
    cudaFuncSetAttribute(k_gemm<64, 32, true, false>, cudaFuncAttributeMaxDynamicSharedMemorySize, s3);
    cudaFuncSetAttribute(k_gemm<32, 16, true, false>, cudaFuncAttributeMaxDynamicSharedMemorySize, s4);

    const int TB = 256;
    const int nb_n = (n + TB - 1) / TB;
    const int nb_e = (e + TB - 1) / TB;
    const int gblk = (n + 63) / 64;

    // ---- CSR build: single edge pass (g_cur is zero on entry) ----
    k_bucketcount<<<nb_e, TB>>>(ei, e, n);
    k_dis<<<nb_n, TB>>>(n);

    // ---- layer 1: agg1 = Ax (width 64), then GEMM 64->96 (+b1) ----
    k_agg<64, false><<<(n * 16 + TB - 1) / TB, TB>>>(x, nullptr, bufA, n);
    k_gemm<64, 96, false, true><<<gblk, 256, s1>>>(bufA, W1, b1, bufB, n);

    // ---- layer 2: t = relu(h1)@W2 ; agg2 = A t + b2 ----
    k_gemm<96, 64, true, false><<<gblk, 256, s2>>>(bufB, W2, nullptr, bufH, n);
    k_agg<64, true><<<(n * 16 + TB - 1) / TB, TB>>>(bufH, b2, bufA, n);

    // ---- layer 3: t = relu(agg2)@W3 ; agg3 = A t + b3 ----
    k_gemm<64, 32, true, false><<<gblk, 256, s3>>>(bufA, W3, nullptr, bufH, n);
    k_agg<32, true><<<(n * 8 + TB - 1) / TB, TB>>>(bufH, b3, bufB, n);

    // ---- layer 4: t = relu(agg3)@W4 ; out = A t + b4 ----
    k_gemm<32, 16, true, false><<<gblk, 256, s4>>>(bufB, W4, nullptr, bufH, n);
    k_agg<16, true><<<(n * 4 + TB - 1) / TB, TB>>>(bufH, b4, out, n);

    // ---- reset cursor for the next (deterministic) replay ----
    k_zero_tail<<<nb_n, TB>>>(n);
}

// round 11
// speedup vs baseline: 1.2087x; 1.0528x over previous
#include <cuda_runtime.h>

typedef unsigned long long ull;

// ---------------- problem constants ------------------------------------------
#define MAX_N 100000
#define MAX_E 1600000
#define MAXDEG 128           // Poisson(16): P(deg>127) ~ 0; guarded anyway
#define LOG2_MAXDEG 7

// ---------------- device scratch (allocation-free; static zero-init) ----------
__device__ int   g_cur[MAX_N];                 // bucket cursor == degree after pass
__device__ float g_dis[MAX_N];                 // (deg+1)^{-1/2}
__device__ int   g_eslot[MAX_N * MAXDEG];      // fixed-stride CSR: src ids
__device__ __align__(16) float g_bufA[MAX_N * 96];
__device__ __align__(16) float g_bufB[MAX_N * 96];
__device__ __align__(16) float g_bufH[MAX_N * 96];

// ---------------- packed f32x2 helpers ----------------------------------------
__device__ __forceinline__ ull pack2(float x) {
    ull r;
    asm("mov.b64 %0, {%1, %1};" : "=l"(r) : "r"(__float_as_uint(x)));
    return r;
}
__device__ __forceinline__ ull fma2(ull a, ull b, ull c) {
    ull d;
    asm("fma.rn.f32x2 %0, %1, %2, %3;" : "=l"(d) : "l"(a), "l"(b), "l"(c));
    return d;
}

// ---------------- single-pass bucket+count ------------------------------------
// edge_index is INT32 (JAX x64 disabled). g_cur must be zero on entry
// (static init on call 1; k_zero_tail re-zeroes at the end of every call).
__global__ void k_bucketcount(const int* __restrict__ ei, int e, int n) {
    int i = blockIdx.x * blockDim.x + threadIdx.x;
    if (i >= e) return;
    int s = ei[i];
    int d = ei[e + i];
    if ((unsigned)s >= (unsigned)n) s = 0;   // surface as rel_err, never trap
    if ((unsigned)d >= (unsigned)n) d = 0;
    int pos = atomicAdd(&g_cur[d], 1);
    if (pos < MAXDEG) g_eslot[(d << LOG2_MAXDEG) + pos] = s;
}

__global__ void k_dis(int n) {
    int i = blockIdx.x * blockDim.x + threadIdx.x;
    if (i < n) g_dis[i] = rsqrtf((float)g_cur[i] + 1.0f);
}

__global__ void k_zero_tail(int n) {
    int i = blockIdx.x * blockDim.x + threadIdx.x;
    if (i < n) g_cur[i] = 0;
}

// ---------------- gather aggregation: out[v] = sum + h[v]*dis^2 (+bias) -------
template <int F, bool BIAS>
__global__ void __launch_bounds__(256)
k_agg(const float* __restrict__ h, const float* __restrict__ bias,
      float* __restrict__ out, int n) {
    constexpr int G = F / 4;
    int tid = blockIdx.x * blockDim.x + threadIdx.x;
    int node = tid / G;
    int v = tid - node * G;
    if (node >= n) return;

    float dn = g_dis[node];
    float d2 = dn * dn;
    float4 acc = *reinterpret_cast<const float4*>(h + (size_t)node * F + (v << 2));
    acc.x *= d2; acc.y *= d2; acc.z *= d2; acc.w *= d2;
    if (BIAS) {
        float4 bv = *reinterpret_cast<const float4*>(bias + (v << 2));
        acc.x += bv.x; acc.y += bv.y; acc.z += bv.z; acc.w += bv.w;
    }

    int deg = g_cur[node];
    if (deg > MAXDEG) deg = MAXDEG;
    const int* slots = g_eslot + ((size_t)node << LOG2_MAXDEG);

    int j = 0;
    for (; j + 4 <= deg; j += 4) {
        int4 s4 = *reinterpret_cast<const int4*>(slots + j);   // 16B-aligned
        float w0 = g_dis[s4.x] * dn;
        float w1 = g_dis[s4.y] * dn;
        float w2 = g_dis[s4.z] * dn;
        float w3 = g_dis[s4.w] * dn;
        float4 a0 = *reinterpret_cast<const float4*>(h + (size_t)s4.x * F + (v << 2));
        float4 a1 = *reinterpret_cast<const float4*>(h + (size_t)s4.y * F + (v << 2));
        float4 a2 = *reinterpret_cast<const float4*>(h + (size_t)s4.z * F + (v << 2));
        float4 a3 = *reinterpret_cast<const float4*>(h + (size_t)s4.w * F + (v << 2));
        acc.x += a0.x * w0; acc.y += a0.y * w0; acc.z += a0.z * w0; acc.w += a0.w * w0;
        acc.x += a1.x * w1; acc.y += a1.y * w1; acc.z += a1.z * w1; acc.w += a1.w * w1;
        acc.x += a2.x * w2; acc.y += a2.y * w2; acc.z += a2.z * w2; acc.w += a2.w * w2;
        acc.x += a3.x * w3; acc.y += a3.y * w3; acc.z += a3.z * w3; acc.w += a3.w * w3;
    }
    for (; j < deg; j++) {
        int s = slots[j];
        float w = g_dis[s] * dn;
        float4 a = *reinterpret_cast<const float4*>(h + (size_t)s * F + (v << 2));
        acc.x += a.x * w; acc.y += a.y * w; acc.z += a.z * w; acc.w += a.w * w;
    }
    *reinterpret_cast<float4*>(out + (size_t)node * F + (v << 2)) = acc;
}

// ---------------- GEMM: out = act(in) @ W (+bh), register-blocked f32x2 --------
// 128-node tile, 256 threads = 8 col-groups x 32 lanes; each thread owns 4 nodes
// (lane, lane+32, lane+64, lane+96) x CH=FOUT/8 columns. Per k: 4 scalar X-LDS
// (conflict-free, stride XP) + NP broadcast W-loads amortized over 4*NP fma2.
template <int FIN, int FOUT, bool RELU, bool BIASH>
__global__ void __launch_bounds__(256)
k_gemm(const float* __restrict__ in, const float* __restrict__ W,
       const float* __restrict__ bh, float* __restrict__ out, int n) {
    constexpr int XP = FIN + 1;          // padded row
    extern __shared__ float sm[];
    float* Xs = sm;                      // [128][XP]
    float* Ws = sm + 128 * XP;           // [FIN][FOUT]
    const int tid = threadIdx.x;
    const int base = blockIdx.x * 128;

    for (int i = tid; i < FIN * FOUT; i += 256) Ws[i] = W[i];

    const int rows = (n - base < 128) ? (n - base) : 128;
    constexpr int KQ = FIN / 4;
    for (int i = tid; i < 128 * KQ; i += 256) {
        int nl = i / KQ;
        int kq = i - nl * KQ;
        float4 v = {0.f, 0.f, 0.f, 0.f};
        if (nl < rows) {
            v = *reinterpret_cast<const float4*>(in + (size_t)(base + nl) * FIN + 4 * kq);
            if (RELU) {
                v.x = fmaxf(v.x, 0.f); v.y = fmaxf(v.y, 0.f);
                v.z = fmaxf(v.z, 0.f); v.w = fmaxf(v.w, 0.f);
            }
        }
        float* xr = Xs + nl * XP + 4 * kq;
        xr[0] = v.x; xr[1] = v.y; xr[2] = v.z; xr[3] = v.w;
    }
    __syncthreads();

    const int lane = tid & 31;           // node sub-index
    const int cg = tid >> 5;             // column group (0..7)
    constexpr int CH = FOUT / 8;         // 12 / 8 / 4 / 2 cols per thread
    constexpr int NP = CH / 2;           // packed accumulators per node (6/4/2/1)
    const int c0 = cg * CH;

    ull acc0[NP], acc1[NP], acc2[NP], acc3[NP];
#pragma unroll
    for (int j = 0; j < NP; j++) {
        ull b = BIASH ? *reinterpret_cast<const ull*>(bh + c0 + 2 * j) : 0ull;
        acc0[j] = b; acc1[j] = b; acc2[j] = b; acc3[j] = b;
    }

    const float* x0p = Xs + (lane +  0) * XP;
    const float* x1p = Xs + (lane + 32) * XP;
    const float* x2p = Xs + (lane + 64) * XP;
    const float* x3p = Xs + (lane + 96) * XP;

#pragma unroll 4
    for (int k = 0; k < FIN; k++) {
        ull xx0 = pack2(x0p[k]);
        ull xx1 = pack2(x1p[k]);
        ull xx2 = pack2(x2p[k]);
        ull xx3 = pack2(x3p[k]);
        const ull* wr = reinterpret_cast<const ull*>(Ws + k * FOUT + c0);
#pragma unroll
        for (int j = 0; j < NP; j++) {
            ull w = wr[j];
            acc0[j] = fma2(xx0, w, acc0[j]);
            acc1[j] = fma2(xx1, w, acc1[j]);
            acc2[j] = fma2(xx2, w, acc2[j]);
            acc3[j] = fma2(xx3, w, acc3[j]);
        }
    }

#pragma unroll
    for (int r = 0; r < 4; r++) {
        int node = base + lane + 32 * r;
        if (node >= n) break;
        ull* acc = (r == 0) ? acc0 : (r == 1) ? acc1 : (r == 2) ? acc2 : acc3;
        ull* op = reinterpret_cast<ull*>(out + (size_t)node * FOUT + c0);
#pragma unroll
        for (int j = 0; j < NP; j++) op[j] = acc[j];
    }
}

// ---------------- launch -------------------------------------------------------
extern "C" void kernel_launch(void* const* d_in, const int* in_sizes, int n_in,
                              void* d_out, int out_size) {
    const float* x  = (const float*)d_in[0];
    const int*   ei = (const int*)d_in[1];   // int32
    const float* W1 = (const float*)d_in[2]; const float* b1 = (const float*)d_in[3];
    const float* W2 = (const float*)d_in[4]; const float* b2 = (const float*)d_in[5];
    const float* W3 = (const float*)d_in[6]; const float* b3 = (const float*)d_in[7];
    const float* W4 = (const float*)d_in[8]; const float* b4 = (const float*)d_in[9];
    float* out = (float*)d_out;

    const int n = in_sizes[0] / 64;
    const int e = in_sizes[1] / 2;

    float *bufA, *bufB, *bufH;
    cudaGetSymbolAddress((void**)&bufA, g_bufA);
    cudaGetSymbolAddress((void**)&bufB, g_bufB);
    cudaGetSymbolAddress((void**)&bufH, g_bufH);

    const int s1 = (128 * 65 + 64 * 96) * 4;   // 57856
    const int s2 = (128 * 97 + 96 * 64) * 4;   // 74240
    const int s3 = (128 * 65 + 64 * 32) * 4;   // 41472
    const int s4 = (128 * 33 + 32 * 16) * 4;   // 18944
    cudaFuncSetAttribute(k_gemm<64, 96, false, true>, cudaFuncAttributeMaxDynamicSharedMemorySize, s1);
    cudaFuncSetAttribute(k_gemm<96, 64, true, false>, cudaFuncAttributeMaxDynamicSharedMemorySize, s2);
    cudaFuncSetAttribute(k_gemm<64, 32, true, false>, cudaFuncAttributeMaxDynamicSharedMemorySize, s3);
    cudaFuncSetAttribute(k_gemm<32, 16, true, false>, cudaFuncAttributeMaxDynamicSharedMemorySize, s4);

    const int TB = 256;
    const int nb_n = (n + TB - 1) / TB;
    const int nb_e = (e + TB - 1) / TB;
    const int gblk = (n + 127) / 128;

    // ---- CSR build: single edge pass (g_cur is zero on entry) ----
    k_bucketcount<<<nb_e, TB>>>(ei, e, n);
    k_dis<<<nb_n, TB>>>(n);

    // ---- layer 1: agg1 = Ax (width 64), then GEMM 64->96 (+b1) ----
    k_agg<64, false><<<(n * 16 + TB - 1) / TB, TB>>>(x, nullptr, bufA, n);
    k_gemm<64, 96, false, true><<<gblk, 256, s1>>>(bufA, W1, b1, bufB, n);

    // ---- layer 2: t = relu(h1)@W2 ; agg2 = A t + b2 ----
    k_gemm<96, 64, true, false><<<gblk, 256, s2>>>(bufB, W2, nullptr, bufH, n);
    k_agg<64, true><<<(n * 16 + TB - 1) / TB, TB>>>(bufH, b2, bufA, n);

    // ---- layer 3: t = relu(agg2)@W3 ; agg3 = A t + b3 ----
    k_gemm<64, 32, true, false><<<gblk, 256, s3>>>(bufA, W3, nullptr, bufH, n);
    k_agg<32, true><<<(n * 8 + TB - 1) / TB, TB>>>(bufH, b3, bufB, n);

    // ---- layer 4: t = relu(agg3)@W4 ; out = A t + b4 ----
    k_gemm<32, 16, true, false><<<gblk, 256, s4>>>(bufB, W4, nullptr, bufH, n);
    k_agg<16, true><<<(n * 4 + TB - 1) / TB, TB>>>(bufH, b4, out, n);

    // ---- reset cursor for the next (deterministic) replay ----
    k_zero_tail<<<nb_n, TB>>>(n);
}